// round 8
// baseline (speedup 1.0000x reference)
#include <cuda_runtime.h>
#include <math.h>

// Problem constants (fixed by the reference)
#define BB 4096
#define TT 200
#define CC 38
#define SS 30
#define FULLMASK 0xffffffffu
#define CTC_BLOCKS 512            // 4096 warps = 1 per sample
#define D_BLOCKS   1024           // 8192 warps = 2 per sample (100 rows each)
#define KL_BLOCKS  15360          // BB*SS/8
#define R1_BLOCKS  240
#define LN2 0.6931471805599453

// Scratch (no cudaMalloc allowed)
__device__ double g_ctcraw[BB];   // log(unnormalized alpha_end); -1e30 = impossible
__device__ double g_d2[BB * 2];   // per-(b,half) sum of log2(D_t)
__device__ float  g_klb[KL_BLOCKS]; // per-block KL partial sums
__device__ double g_part[R1_BLOCKS];

__device__ __forceinline__ float warp_sum(float v) {
#pragma unroll
    for (int o = 16; o > 0; o >>= 1) v += __shfl_xor_sync(FULLMASK, v, o);
    return v;
}

// ---------------------------------------------------------------------------
// fp64 fallback for underflowed samples (rare). Writes raw log (no D, no
// zero_infinity -- both applied in reduce1).
// ---------------------------------------------------------------------------
__device__ __noinline__ double ctc_fp64(
    const float* __restrict__ xp, int tg, bool skip, int il, int tl)
{
    const int lane = threadIdx.x & 31;
    double ae = (lane == 0) ? 1.0 : 0.0;
    double ao = 0.0;
    for (int t = 0; t < il; ++t) {
        const float* r = xp + (size_t)t * CC;
        float pbe = __expf(r[0] - 2.0f);
        float ple = __expf(r[tg] - 2.0f);
        double op = __shfl_up_sync(FULLMASK, ao, 1);
        if (lane == 0) op = 0.0;
        double ne = (ae + op) * (double)pbe;
        double no = (ao + ae + (skip ? op : 0.0)) * (double)ple;
        ae = (lane <= 30) ? ne : 0.0;
        ao = (lane < 30) ? no : 0.0;
    }
    double aev = __shfl_sync(FULLMASK, ae, tl);
    double aov = __shfl_sync(FULLMASK, ao, tl - 1);
    double s = aev + aov;
    return (s > 0.0) ? log(s) : -1e30;
}

// ---------------------------------------------------------------------------
// CTC recursion, one warp per sample. fp32 alpha, deferred exponent renorm:
// the warp_max for the scale is computed from step-3 alphas and its 5-shfl
// reduction overlaps steps 4..7; the (stale but warp-uniform, hence exactly
// correct) power-of-2 scale is applied at group end. Writes raw log only.
// ---------------------------------------------------------------------------
__device__ __forceinline__ void ctc_body(
    const float* __restrict__ x, const int* __restrict__ target,
    const int* __restrict__ ilen, const int* __restrict__ tlen, int b)
{
    const int lane = threadIdx.x & 31;

    int tg  = (lane < SS) ? target[b * SS + lane] : 1;
    int tgp = __shfl_up_sync(FULLMASK, tg, 1);
    const bool skip = (lane == 0 || tg != tgp);

    const int il = ilen[b];
    const int tl = tlen[b];
    const float* xp = x + (size_t)b * TT * CC;

    float ae = (lane == 0) ? 1.0f : 0.0f;
    float ao = 0.0f;
    int   Esum = 0;                      // true alpha = stored * 2^Esum

    auto step = [&](float pbraw, float plraw) {
        float pbe = __expf(pbraw - 2.0f);
        float ple = __expf(plraw - 2.0f);
        float op  = __shfl_up_sync(FULLMASK, ao, 1);
        if (lane == 0) op = 0.0f;
        float s  = ae + op;
        float ne = s * pbe;
        float u  = (skip ? s : ae) + ao;      // = ao + ae + skip*op
        ae = ne;
        ao = u * ple;
    };
    // Apply a warp-uniform 2^k rescale derived from max m (stale is fine).
    auto apply = [&](float m) {
        unsigned mb = __float_as_uint(m);
        if (mb >= 0x00800000u) {              // m normal, > 0
            int e = (int)((mb >> 23) & 0xff) - 127;
            int k = 80 - e;                   // re-center at 2^80
            k = (k > 127) ? 127 : (k < -126 ? -126 : k);
            float sc = __uint_as_float((unsigned)(127 + k) << 23);
            ae *= sc; ao *= sc;
            Esum -= k;
        }
    };

    if (il == TT) {
        float cpb[8], cpl[8];
#pragma unroll
        for (int i = 0; i < 8; ++i) {
            cpb[i] = xp[i * CC];
            cpl[i] = xp[i * CC + tg];
        }
        for (int g = 0; g < TT / 8; ++g) {
            float npb[8], npl[8];
            if (g + 1 < TT / 8) {
                const float* np = xp + (size_t)(g + 1) * 8 * CC;
#pragma unroll
                for (int i = 0; i < 8; ++i) {
                    npb[i] = np[i * CC];
                    npl[i] = np[i * CC + tg];
                }
            } else {
#pragma unroll
                for (int i = 0; i < 8; ++i) { npb[i] = 0.0f; npl[i] = 0.0f; }
            }
            step(cpb[0], cpl[0]);
            step(cpb[1], cpl[1]);
            step(cpb[2], cpl[2]);
            step(cpb[3], cpl[3]);
            // start the (deferred) max reduction; overlaps steps 4..7
            float m = fmaxf(ae, ao);
            step(cpb[4], cpl[4]);
            m = fmaxf(m, __shfl_xor_sync(FULLMASK, m, 16));
            step(cpb[5], cpl[5]);
            m = fmaxf(m, __shfl_xor_sync(FULLMASK, m, 8));
            step(cpb[6], cpl[6]);
            m = fmaxf(m, __shfl_xor_sync(FULLMASK, m, 4));
            step(cpb[7], cpl[7]);
            m = fmaxf(m, __shfl_xor_sync(FULLMASK, m, 2));
            m = fmaxf(m, __shfl_xor_sync(FULLMASK, m, 1));
            apply(m);
#pragma unroll
            for (int i = 0; i < 8; ++i) { cpb[i] = npb[i]; cpl[i] = npl[i]; }
        }
    } else {
        for (int t = 0; t < il; ++t) {
            const float* r = xp + (size_t)t * CC;
            step(r[0], r[tg]);
            if ((t & 7) == 7) {
                float m = fmaxf(ae, ao);
#pragma unroll
                for (int o = 16; o > 0; o >>= 1)
                    m = fmaxf(m, __shfl_xor_sync(FULLMASK, m, o));
                apply(m);
            }
        }
    }

    float aev = __shfl_sync(FULLMASK, ae, tl);       // state 2*tl
    float aov = __shfl_sync(FULLMASK, ao, tl - 1);   // state 2*tl-1
    double ssum = (double)aev + (double)aov;

    if (ssum >= 8.673617379884035e-19 /* 2^-60 stored units */) {
        if (lane == 0)
            g_ctcraw[b] = log(ssum) + (double)Esum * LN2;
    } else {
        double raw = ctc_fp64(xp, tg, skip, il, tl);
        if (lane == 0) g_ctcraw[b] = raw;
    }
}

// ---------------------------------------------------------------------------
// Softmax-denominator pass: warp w -> sample b=w/2, rows [h*100, h*100+100).
// ---------------------------------------------------------------------------
__device__ __forceinline__ void d_body(
    const float* __restrict__ x, const int* __restrict__ ilen, int w)
{
    const int lane = threadIdx.x & 31;
    const int b = w >> 1;
    const int t0 = (w & 1) * 100;
    const int il = ilen[b];
    const int tend = (il < t0 + 100) ? il : (t0 + 100);

    const float* xp = x + (size_t)b * TT * CC;
    float sumL2 = 0.0f, sumC = 0.0f;

    int t = t0;
    for (; t + 2 <= tend; t += 2) {
        const float* r0 = xp + (size_t)t * CC;
        const float* r1 = r0 + CC;
        float a1 = r0[lane];
        float a2 = (lane < 6) ? r0[32 + lane] : -1e30f;
        float b1 = r1[lane];
        float b2 = (lane < 6) ? r1[32 + lane] : -1e30f;
        float ea = __expf(a1 - 2.0f) + __expf(a2 - 2.0f);
        float eb = __expf(b1 - 2.0f) + __expf(b2 - 2.0f);
        float Da = warp_sum(ea);
        float Db = warp_sum(eb);
        float y = (__log2f(Da) + __log2f(Db)) - sumC;
        float s = sumL2 + y;
        sumC = (s - sumL2) - y;
        sumL2 = s;
    }
    for (; t < tend; ++t) {
        const float* r0 = xp + (size_t)t * CC;
        float a1 = r0[lane];
        float a2 = (lane < 6) ? r0[32 + lane] : -1e30f;
        float D = warp_sum(__expf(a1 - 2.0f) + __expf(a2 - 2.0f));
        float y = __log2f(D) - sumC;
        float s = sumL2 + y;
        sumC = (s - sumL2) - y;
        sumL2 = s;
    }
    if (lane == 0) g_d2[w] = (double)sumL2 - (double)sumC;
}

// ---------------------------------------------------------------------------
// KL smoothing: one warp per (b,s); per-BLOCK sum written to g_klb.
// ---------------------------------------------------------------------------
__device__ __forceinline__ float kl_val(
    const float* __restrict__ x, const int* __restrict__ target,
    const int* __restrict__ tlen, const int* __restrict__ pos,
    const float* __restrict__ ms, int idx)
{
    const int lane = threadIdx.x & 31;
    const int b = idx / SS;
    const int s = idx - b * SS;

    const int tl = tlen[b];
    if (s >= tl) return 0.0f;

    const int p  = pos[b * SS + s];
    const int tg = target[b * SS + s];
    const int f  = (s == 0) ? (CC - 1) : target[b * SS + s - 1];

    const float* row = x + ((size_t)b * TT + p) * CC;
    float x1 = row[lane];
    float x2 = (lane < 6) ? row[32 + lane] : 0.0f;
    float e1 = __expf(x1);
    float e2 = (lane < 6) ? __expf(x2) : 0.0f;
    float lse = __logf(warp_sum(e1 + e2));

    const float* msr = ms + ((size_t)(f - 1) * 37 + (tg - 1)) * 37;
    float s1 = (lane >= 1) ? msr[lane - 1] : 0.0f;   // class c = lane
    float s2 = (lane < 6) ? msr[lane + 31] : 0.0f;   // class c = lane + 32

    float t1 = s1 + 1e-10f;
    float term = t1 * (__logf(t1) - (x1 - lse));
    float wp = s1;
    if (lane < 6) {
        float t2 = s2 + 1e-10f;
        term += t2 * (__logf(t2) - (x2 - lse));
        wp += s2;
    }
    float tsum = warp_sum(term);
    float wsum = warp_sum(wp);
    float L = (float)tl;
    float smooth = -expm1f(-0.05129329438755058f / L);  // 1 - 0.95^(1/L)
    return (smooth / L) * (wsum * tsum * (1.0f / (float)CC));
}

// ---------------------------------------------------------------------------
// Mega-fused kernel: CTC (latency-bound, ~no BW) + D-pass + KL (BW/issue
// bound) co-resident so they backfill each other.
// ---------------------------------------------------------------------------
__global__ void __launch_bounds__(256) mega_kernel(
    const float* __restrict__ x, const int* __restrict__ target,
    const int* __restrict__ ilen, const int* __restrict__ tlen,
    const int* __restrict__ pos, const float* __restrict__ ms)
{
    const int warp = threadIdx.x >> 5;
    if (blockIdx.x < CTC_BLOCKS) {
        ctc_body(x, target, ilen, tlen, blockIdx.x * 8 + warp);
    } else if (blockIdx.x < CTC_BLOCKS + D_BLOCKS) {
        d_body(x, ilen, (blockIdx.x - CTC_BLOCKS) * 8 + warp);
    } else {
        const int kb = blockIdx.x - CTC_BLOCKS - D_BLOCKS;
        float v = kl_val(x, target, tlen, pos, ms, kb * 8 + warp);
        __shared__ float ksum[8];
        if ((threadIdx.x & 31) == 0) ksum[warp] = v;
        __syncthreads();
        if (threadIdx.x == 0) {
            float t = 0.0f;
#pragma unroll
            for (int i = 0; i < 8; ++i) t += ksum[i];
            g_klb[kb] = t;
        }
    }
}

// ---------------------------------------------------------------------------
// Deterministic two-stage reduction. reduce1 also finalizes each sample's
// nll: nll = -(raw - lnD_total), zero_infinity, /tl, mean.
// ---------------------------------------------------------------------------
__global__ void __launch_bounds__(256) reduce1_kernel(const int* __restrict__ tlen)
{
    __shared__ double sm[256];
    const int tid = threadIdx.x;
    double acc = 0.0;
    for (int i = blockIdx.x * 256 + tid; i < KL_BLOCKS; i += R1_BLOCKS * 256)
        acc += (double)g_klb[i];
    for (int b = blockIdx.x * 256 + tid; b < BB; b += R1_BLOCKS * 256) {
        double lnD = (g_d2[2 * b] + g_d2[2 * b + 1]) * LN2;
        double nll = -(g_ctcraw[b] - lnD);
        if (nll > 1e8) nll = 0.0;                    // zero_infinity
        acc += (nll / (double)tlen[b]) * (1.0 / (double)BB);
    }
    sm[tid] = acc;
    __syncthreads();
    for (int st = 128; st > 0; st >>= 1) {
        if (tid < st) sm[tid] += sm[tid + st];
        __syncthreads();
    }
    if (tid == 0) g_part[blockIdx.x] = sm[0];
}

__global__ void __launch_bounds__(256) reduce2_kernel(float* __restrict__ out)
{
    __shared__ double sm[256];
    const int tid = threadIdx.x;
    sm[tid] = (tid < R1_BLOCKS) ? g_part[tid] : 0.0;
    __syncthreads();
    for (int st = 128; st > 0; st >>= 1) {
        if (tid < st) sm[tid] += sm[tid + st];
        __syncthreads();
    }
    if (tid == 0) out[0] = (float)sm[0];
}

// ---------------------------------------------------------------------------
extern "C" void kernel_launch(void* const* d_in, const int* in_sizes, int n_in,
                              void* d_out, int out_size)
{
    const float* x      = (const float*)d_in[0];   // [B,T,C] f32
    const int*   target = (const int*)d_in[1];     // [B,S]   i32
    const int*   ilen   = (const int*)d_in[2];     // [B]     i32
    const int*   tlen   = (const int*)d_in[3];     // [B]     i32
    const int*   pos    = (const int*)d_in[4];     // [B,S]   i32
    const float* ms     = (const float*)d_in[5];   // [37,37,37] f32

    mega_kernel<<<CTC_BLOCKS + D_BLOCKS + KL_BLOCKS, 256>>>(
        x, target, ilen, tlen, pos, ms);
    reduce1_kernel<<<R1_BLOCKS, 256>>>(tlen);
    reduce2_kernel<<<1, 256>>>((float*)d_out);
}

// round 9
// speedup vs baseline: 1.1798x; 1.1798x over previous
#include <cuda_runtime.h>
#include <math.h>

// Problem constants (fixed by the reference)
#define BB 4096
#define TT 200
#define CC 38
#define SS 30
#define FULLMASK 0xffffffffu
#define CTC_BLOCKS 512            // 4096 warps = 1 per sample
#define D_BLOCKS   1024           // 8192 warps = 2 per sample (100 rows each)
#define KL_BLOCKS  15360          // BB*SS/8
#define TAB_N      1369           // 37*37
#define LN2 0.6931471805599453

// Scratch (no cudaMalloc allowed)
__device__ double g_ctcraw[BB];     // log(unnormalized alpha_end); -1e30 = impossible
__device__ double g_d2[BB * 2];     // per-(b,halfT) sum of log2(D_t)
__device__ float  g_klb[KL_BLOCKS]; // per-block KL partial sums
__device__ float4 g_tab[TAB_N];     // per (prev,cur) label pair: {H, W, S, 0}

__device__ __forceinline__ float warp_sum(float v) {
#pragma unroll
    for (int o = 16; o > 0; o >>= 1) v += __shfl_xor_sync(FULLMASK, v, o);
    return v;
}

// ---------------------------------------------------------------------------
// Table kernel: for each (f,tg) in 1..37 x 1..37, with t_c = SLS_c + 1e-10:
//   H = sum_c t_c * ln(t_c)   (incl. c=0 where SLS_0=0)
//   W = sum_c t_c
//   S = sum_c SLS_c
// ---------------------------------------------------------------------------
__global__ void __launch_bounds__(256) table_kernel(const float* __restrict__ ms)
{
    const int lane = threadIdx.x & 31;
    const int idx = blockIdx.x * 8 + (threadIdx.x >> 5);
    if (idx >= TAB_N) return;
    const float* msr = ms + (size_t)idx * 37;

    float m1 = msr[lane < 32 ? lane : 0];          // indices 0..31 (lane<32 always)
    float m2 = (lane < 5) ? msr[lane + 32] : 0.0f; // indices 32..36
    float t1 = m1 + 1e-10f;
    float H = t1 * __logf(t1);
    float W = t1;
    float S = m1;
    if (lane < 5) {
        float t2 = m2 + 1e-10f;
        H += t2 * __logf(t2);
        W += t2;
        S += m2;
    }
    H = warp_sum(H); W = warp_sum(W); S = warp_sum(S);
    if (lane == 0) {
        H += -2.302585093e-9f;   // c=0 term: 1e-10 * ln(1e-10)
        W += 1e-10f;             // c=0 term
        g_tab[idx] = make_float4(H, W, S, 0.0f);
    }
}

// ---------------------------------------------------------------------------
// fp64 fallback (proven numerics): rerun one sample's full CTC forward with
// explicit emissions exp(x-2). Returns raw log(alpha_end). Rare.
// ---------------------------------------------------------------------------
__device__ __noinline__ double ctc_fp64(
    const float* __restrict__ xp, const int* __restrict__ target,
    int b, int il, int tl)
{
    const int lane = threadIdx.x & 31;
    int tg  = (lane < SS) ? target[b * SS + lane] : 1;
    int tgp = __shfl_up_sync(FULLMASK, tg, 1);
    const bool skip = (lane == 0 || tg != tgp);

    double ae = (lane == 0) ? 1.0 : 0.0;
    double ao = 0.0;
    for (int t = 0; t < il; ++t) {
        const float* r = xp + (size_t)t * CC;
        float pbe = __expf(r[0] - 2.0f);
        float ple = __expf(r[tg] - 2.0f);
        double op = __shfl_up_sync(FULLMASK, ao, 1);
        if (lane == 0) op = 0.0;
        double ne = (ae + op) * (double)pbe;
        double no = (ao + ae + (skip ? op : 0.0)) * (double)ple;
        ae = (lane <= 30) ? ne : 0.0;
        ao = (lane < 30) ? no : 0.0;
    }
    double aev = __shfl_sync(FULLMASK, ae, tl);
    double aov = __shfl_sync(FULLMASK, ao, tl - 1);
    double s = aev + aov;
    return (s > 0.0) ? log(s) : -1e30;
}

// ---------------------------------------------------------------------------
// CTC recursion (beta form), one warp per sample.
// beta = alpha / prod_t exp(x0_t - 2): even update is a pure ADD, odd
// multiplier is exp(x_tg - x0) -> ONE MUFU per step. Lane mapping shifted:
// lane i (1..31) holds states 2(i-1) [even] and 2(i-1)+1 [odd]; lane 0 is a
// constant-zero boundary so shfl_up needs no select. Deferred power-of-2
// renorm (stale max is exactly correct). Blank log-sum accumulated as plain
// adds per prefetch group (Kahan). Writes raw log(alpha_end) only.
// ---------------------------------------------------------------------------
__device__ __forceinline__ void ctc_body(
    const float* __restrict__ x, const int* __restrict__ target,
    const int* __restrict__ ilen, const int* __restrict__ tlen, int b)
{
    const int lane = threadIdx.x & 31;
    const bool valid = (lane >= 1 && lane <= SS);    // lanes with a real odd state

    int tg  = valid ? target[b * SS + (lane - 1)] : 1;
    int tgp = __shfl_up_sync(FULLMASK, tg, 1);
    const float skipf = (lane == 1 || tg != tgp) ? 1.0f : 0.0f;

    const int il = ilen[b];
    const int tl = tlen[b];
    const float* xp = x + (size_t)b * TT * CC;

    float ae = (lane == 1) ? 1.0f : 0.0f;   // beta[2(lane-1)]
    float ao = 0.0f;                        // beta[2(lane-1)+1]
    int   Esum = 0;                         // true beta = stored * 2^Esum
    float bs = 0.0f, bsc = 0.0f;            // Kahan sum of (x0_t - 2)

    auto step = [&](float d) {
        float e  = __expf(d);                        // p_l / p_b
        float op = __shfl_up_sync(FULLMASK, ao, 1);  // lane0: own ao = 0
        float v  = ae + ao;                          // off-chain
        ae = ae + op;
        ao = fmaf(skipf, op, v) * e;
    };
    auto apply = [&](float m) {   // warp-uniform 2^k rescale, center 2^30
        unsigned mb = __float_as_uint(m);
        if (mb >= 0x00800000u && mb < 0x7f800000u) {
            int e = (int)(mb >> 23) - 127;
            int k = 30 - e;
            k = (k > 127) ? 127 : (k < -126 ? -126 : k);
            float sc = __uint_as_float((unsigned)(127 + k) << 23);
            ae *= sc; ao *= sc;
            Esum -= k;
        }
    };
    auto kadd = [&](float y0) {   // Kahan add into (bs, bsc)
        float y = y0 - bsc;
        float t = bs + y;
        bsc = (t - bs) - y;
        bs = t;
    };

    if (il == TT) {
        float cd[8]; float cbs;
        {
            float g = 0.0f;
#pragma unroll
            for (int i = 0; i < 8; ++i) {
                float b0 = xp[i * CC];
                float tv = xp[i * CC + tg];
                cd[i] = valid ? (tv - b0) : -1e30f;   // -1e30 kills ghost lanes
                g += b0;
            }
            cbs = g - 16.0f;
        }
        for (int g = 0; g < TT / 8; ++g) {
            float nd[8]; float nbs = 0.0f;
            if (g + 1 < TT / 8) {
                const float* np = xp + (size_t)(g + 1) * 8 * CC;
                float gsum = 0.0f;
#pragma unroll
                for (int i = 0; i < 8; ++i) {
                    float b0 = np[i * CC];
                    float tv = np[i * CC + tg];
                    nd[i] = valid ? (tv - b0) : -1e30f;
                    gsum += b0;
                }
                nbs = gsum - 16.0f;
            } else {
#pragma unroll
                for (int i = 0; i < 8; ++i) nd[i] = -1e30f;
            }
            kadd(cbs);
            step(cd[0]);
            step(cd[1]);
            step(cd[2]);
            step(cd[3]);
            // deferred max: measured here, butterfly overlaps steps 4..7
            float m = fmaxf(ae, ao);
            step(cd[4]);
            m = fmaxf(m, __shfl_xor_sync(FULLMASK, m, 16));
            step(cd[5]);
            m = fmaxf(m, __shfl_xor_sync(FULLMASK, m, 8));
            step(cd[6]);
            m = fmaxf(m, __shfl_xor_sync(FULLMASK, m, 4));
            step(cd[7]);
            m = fmaxf(m, __shfl_xor_sync(FULLMASK, m, 2));
            m = fmaxf(m, __shfl_xor_sync(FULLMASK, m, 1));
            apply(m);
#pragma unroll
            for (int i = 0; i < 8; ++i) cd[i] = nd[i];
            cbs = nbs;
        }
    } else {
        for (int t = 0; t < il; ++t) {
            const float* r = xp + (size_t)t * CC;
            float b0 = r[0];
            float d = valid ? (r[tg] - b0) : -1e30f;
            kadd(b0 - 2.0f);
            step(d);
            if ((t & 7) == 7) {
                float m = fmaxf(ae, ao);
#pragma unroll
                for (int o = 16; o > 0; o >>= 1)
                    m = fmaxf(m, __shfl_xor_sync(FULLMASK, m, o));
                apply(m);
            }
        }
    }

    // state 2*tl (even) -> lane tl+1 ; state 2*tl-1 (odd) -> lane tl
    float aev = __shfl_sync(FULLMASK, ae, tl + 1);
    float aov = __shfl_sync(FULLMASK, ao, tl);
    double ssum = (double)aev + (double)aov;

    // Accept only finite values comfortably above the flush floor.
    if (ssum >= 8.673617379884035e-19 /* 2^-60 */ && ssum < 6.0e38) {
        if (lane == 0)
            g_ctcraw[b] = log(ssum) + (double)Esum * LN2 + (double)bs;
    } else {
        double raw = ctc_fp64(xp, target, b, il, tl);
        if (lane == 0) g_ctcraw[b] = raw;
    }
}

// ---------------------------------------------------------------------------
// Softmax-denominator pass, width-16: warp w -> sample b=w/2, 100 rows.
// Half-warps process two consecutive rows concurrently (float2 + tail),
// 4-shfl butterfly per row, running product P with exponent stripping.
// ---------------------------------------------------------------------------
__device__ __forceinline__ void d_body(
    const float* __restrict__ x, const int* __restrict__ ilen, int w)
{
    const int lane = threadIdx.x & 31;
    const int sub  = lane & 15;
    const int half = lane >> 4;
    const int b  = w >> 1;
    const int t0 = (w & 1) * 100;
    const int il = ilen[b];
    const int tend = (il < t0 + 100) ? il : (t0 + 100);

    const float* xp = x + (size_t)b * TT * CC;
    float P = 1.0f;
    int   Le = 0;
    int   it = 0;

    int t = t0;
    for (; t + 2 <= tend; t += 2, ++it) {
        const float* rb = xp + (size_t)(t + half) * CC;
        float2 v = ((const float2*)rb)[sub];                 // floats 2s,2s+1 (0..31)
        float tail = (sub >= 10) ? rb[22 + sub] : -1e30f;    // floats 32..37
        float e = __expf(v.x - 2.0f) + __expf(v.y - 2.0f) + __expf(tail - 2.0f);
#pragma unroll
        for (int o = 8; o > 0; o >>= 1)                      // within-half butterfly
            e += __shfl_xor_sync(FULLMASK, e, o);
        P *= e;                                              // own half's row sum
        if ((it & 7) == 7) {                                 // strip exponent
            unsigned pb = __float_as_uint(P);
            Le += (int)(pb >> 23) - 127;
            P = __uint_as_float((pb & 0x807fffffu) | 0x3f800000u);
        }
    }
    if (t < tend) {                                          // odd remainder: half 0 only
        if (half == 0) {
            const float* rb = xp + (size_t)t * CC;
            float2 v = ((const float2*)rb)[sub];
            float tail = (sub >= 10) ? rb[22 + sub] : -1e30f;
            float e = __expf(v.x - 2.0f) + __expf(v.y - 2.0f) + __expf(tail - 2.0f);
#pragma unroll
            for (int o = 8; o > 0; o >>= 1)
                e += __shfl_xor_sync(0x0000ffffu, e, o);
            P *= e;
        }
    }
    double l2 = (double)Le + log2((double)P);
    double other = __shfl_xor_sync(FULLMASK, l2, 16);
    if (lane == 0) g_d2[w] = l2 + other;                     // sum of both halves
}

// ---------------------------------------------------------------------------
// KL smoothing: one warp per (b,s); lane l holds classes 2l, 2l+1 (l<19).
// Uses the precomputed (H,W,S) table; reduces only (sum exp, sum t*x).
// ---------------------------------------------------------------------------
__device__ __forceinline__ float kl_val(
    const float* __restrict__ x, const int* __restrict__ target,
    const int* __restrict__ tlen, const int* __restrict__ pos,
    const float* __restrict__ ms, int idx)
{
    const int lane = threadIdx.x & 31;
    const int b = idx / SS;
    const int s = idx - b * SS;

    const int tl = tlen[b];
    if (s >= tl) return 0.0f;

    const int p  = pos[b * SS + s];
    const int tg = target[b * SS + s];
    const int f  = (s == 0) ? (CC - 1) : target[b * SS + s - 1];

    const float* row = x + ((size_t)b * TT + p) * CC;
    const float* msr = ms + ((size_t)(f - 1) * 37 + (tg - 1)) * 37;

    float Ev = 0.0f, Xv = 0.0f;
    if (lane < 19) {
        float2 xv = ((const float2*)row)[lane];
        float se = (lane == 0) ? 0.0f : msr[2 * lane - 1];   // SLS class 2l
        float so = msr[2 * lane];                            // SLS class 2l+1
        float te = se + 1e-10f;
        float to = so + 1e-10f;
        Ev = __expf(xv.x) + __expf(xv.y);
        Xv = te * xv.x + to * xv.y;
    }
#pragma unroll
    for (int o = 16; o > 0; o >>= 1) {
        Ev += __shfl_xor_sync(FULLMASK, Ev, o);
        Xv += __shfl_xor_sync(FULLMASK, Xv, o);
    }
    float lse = __logf(Ev);
    float4 tb = g_tab[(f - 1) * 37 + (tg - 1)];              // {H, W, S}
    float klrow = (tb.x - Xv + lse * tb.y) * (1.0f / (float)CC);
    float L = (float)tl;
    float smooth = -expm1f(-0.05129329438755058f / L);       // 1 - 0.95^(1/L)
    return (smooth / L) * tb.z * klrow;
}

// ---------------------------------------------------------------------------
// Mega-fused kernel.
// ---------------------------------------------------------------------------
__global__ void __launch_bounds__(256) mega_kernel(
    const float* __restrict__ x, const int* __restrict__ target,
    const int* __restrict__ ilen, const int* __restrict__ tlen,
    const int* __restrict__ pos, const float* __restrict__ ms)
{
    const int warp = threadIdx.x >> 5;
    if (blockIdx.x < CTC_BLOCKS) {
        ctc_body(x, target, ilen, tlen, blockIdx.x * 8 + warp);
    } else if (blockIdx.x < CTC_BLOCKS + D_BLOCKS) {
        d_body(x, ilen, (blockIdx.x - CTC_BLOCKS) * 8 + warp);
    } else {
        const int kb = blockIdx.x - CTC_BLOCKS - D_BLOCKS;
        float v = kl_val(x, target, tlen, pos, ms, kb * 8 + warp);
        __shared__ float ksum[8];
        if ((threadIdx.x & 31) == 0) ksum[warp] = v;
        __syncthreads();
        if (threadIdx.x == 0) {
            float t = 0.0f;
#pragma unroll
            for (int i = 0; i < 8; ++i) t += ksum[i];
            g_klb[kb] = t;
        }
    }
}

// ---------------------------------------------------------------------------
// Single-block deterministic final reduction + per-sample nll finalize.
// ---------------------------------------------------------------------------
__global__ void __launch_bounds__(1024) finalize_kernel(
    const int* __restrict__ tlen, float* __restrict__ out)
{
    __shared__ double sm[1024];
    const int tid = threadIdx.x;
    double acc = 0.0;
    for (int i = tid; i < KL_BLOCKS; i += 1024)
        acc += (double)g_klb[i];
    for (int b = tid; b < BB; b += 1024) {
        double lnD = (g_d2[2 * b] + g_d2[2 * b + 1]) * LN2;
        double nll = -(g_ctcraw[b] - lnD);
        if (nll > 1e8) nll = 0.0;                            // zero_infinity
        acc += (nll / (double)tlen[b]) * (1.0 / (double)BB);
    }
    sm[tid] = acc;
    __syncthreads();
    for (int st = 512; st > 0; st >>= 1) {
        if (tid < st) sm[tid] += sm[tid + st];
        __syncthreads();
    }
    if (tid == 0) out[0] = (float)sm[0];
}

// ---------------------------------------------------------------------------
extern "C" void kernel_launch(void* const* d_in, const int* in_sizes, int n_in,
                              void* d_out, int out_size)
{
    const float* x      = (const float*)d_in[0];   // [B,T,C] f32
    const int*   target = (const int*)d_in[1];     // [B,S]   i32
    const int*   ilen   = (const int*)d_in[2];     // [B]     i32
    const int*   tlen   = (const int*)d_in[3];     // [B]     i32
    const int*   pos    = (const int*)d_in[4];     // [B,S]   i32
    const float* ms     = (const float*)d_in[5];   // [37,37,37] f32

    table_kernel<<<(TAB_N + 7) / 8, 256>>>(ms);
    mega_kernel<<<CTC_BLOCKS + D_BLOCKS + KL_BLOCKS, 256>>>(
        x, target, ilen, tlen, pos, ms);
    finalize_kernel<<<1, 1024>>>(tlen, (float*)d_out);
}